// round 9
// baseline (speedup 1.0000x reference)
#include <cuda_runtime.h>
#include <cuda_fp16.h>
#include <stdint.h>

#define BATCH 4
#define SEQ   2048
#define DIM   768
#define MROWS 8192            // B*S
#define NQKV  2304            // 3*DIM

// ---------------- device scratch: fp16 planes --------------------------------
// A-side operands are split (hi+lo); B-side operands are single fp16 planes.
__device__ __align__(128) __half g_xh[(long)MROWS * DIM];
__device__ __align__(128) __half g_xl[(long)MROWS * DIM];
__device__ __align__(128) __half g_wh[(long)NQKV * DIM];            // W rounded
__device__ __align__(128) __half g_qh[(long)MROWS * DIM];
__device__ __align__(128) __half g_ql[(long)MROWS * DIM];
__device__ __align__(128) __half g_kh[(long)MROWS * DIM];           // K rounded
__device__ __align__(128) __half g_vh[(long)MROWS * DIM];           // V rounded, [b*S+s][d]
__device__ __align__(128) __half g_ph[(size_t)BATCH * SEQ * SEQ];
__device__ __align__(128) __half g_pl[(size_t)BATCH * SEQ * SEQ];
__device__ float g_S[(size_t)BATCH * SEQ * SEQ];

// ---------------- PTX helpers (portable, no arch-'a' features) --------------
__device__ __forceinline__ uint32_t smem_u32(const void* p) {
    uint32_t a;
    asm("{ .reg .u64 t; cvta.to.shared.u64 t, %1; cvt.u32.u64 %0, t; }"
        : "=r"(a) : "l"(p));
    return a;
}
__device__ __forceinline__ void ldsm4(uint32_t r[4], uint32_t addr) {
    asm volatile("ldmatrix.sync.aligned.m8n8.x4.shared.b16 {%0,%1,%2,%3}, [%4];"
                 : "=r"(r[0]), "=r"(r[1]), "=r"(r[2]), "=r"(r[3]) : "r"(addr));
}
__device__ __forceinline__ void ldsm4t(uint32_t r[4], uint32_t addr) {
    asm volatile("ldmatrix.sync.aligned.m8n8.x4.trans.shared.b16 {%0,%1,%2,%3}, [%4];"
                 : "=r"(r[0]), "=r"(r[1]), "=r"(r[2]), "=r"(r[3]) : "r"(addr));
}
__device__ __forceinline__ void mma16816(float d[4], const uint32_t a[4],
                                         const uint32_t b[2]) {
    asm volatile(
        "mma.sync.aligned.m16n8k16.row.col.f32.f16.f16.f32 "
        "{%0,%1,%2,%3}, {%4,%5,%6,%7}, {%8,%9}, {%0,%1,%2,%3};"
        : "+f"(d[0]), "+f"(d[1]), "+f"(d[2]), "+f"(d[3])
        : "r"(a[0]), "r"(a[1]), "r"(a[2]), "r"(a[3]), "r"(b[0]), "r"(b[1]));
}
__device__ __forceinline__ void split_f16(float v, __half& h, __half& l) {
    h = __float2half_rn(v);
    l = __float2half_rn(v - __half2float(h));
}

// ---------------- smem geometry: k32 stages, double buffered -----------------
// tiles: 128 rows x 32 k fp16, pitch 40 halves (80B) -> conflict-free ldmatrix.
#define ROW2B   80
#define PLANE2  10240                      // 128*80
#define MAT2A   (2 * PLANE2)               // A hi+lo = 20480
#define NT_STG  (MAT2A + PLANE2)           // A(2) + B(1) = 30720
#define NT_SMEM (2 * NT_STG)               // 61440

#define VROWB   272
#define VPLANE2 (32 * VROWB)               // 8704 (single V plane, 32 rows)
#define PV_STG  (MAT2A + VPLANE2)          // 29184
#define PV_SMEM (2 * PV_STG)               // 58368

// ---------------- stage compute: warp tile 64x32, one k16 sub-block ----------
// A split (planes at sa, sa+PLANE2); B single plane at sb. 2 MMAs per (mi,nj).
__device__ __forceinline__ void stage_nt(uint32_t sa, uint32_t sb, int sub, int lane,
                                         int wm, int wn, float acc[4][4][4]) {
    const int lr = lane & 15;
    const uint32_t lc16 = ((lane >> 4) << 4) + (uint32_t)sub * 32;
    uint32_t bh[4][2];
#pragma unroll
    for (int j = 0; j < 2; ++j) {
        uint32_t t4[4];
        const uint32_t roff = (uint32_t)(wn * 32 + j * 16 + lr) * ROW2B + lc16;
        ldsm4(t4, sb + roff);
        bh[j*2][0] = t4[0]; bh[j*2+1][0] = t4[1];
        bh[j*2][1] = t4[2]; bh[j*2+1][1] = t4[3];
    }
#pragma unroll
    for (int mi = 0; mi < 4; ++mi) {
        uint32_t ah[4], al[4];
        const uint32_t roff = (uint32_t)(wm * 64 + mi * 16 + lr) * ROW2B + lc16;
        ldsm4(ah, sa + roff);
        ldsm4(al, sa + PLANE2 + roff);
#pragma unroll
        for (int nj = 0; nj < 4; ++nj) {
            mma16816(acc[mi][nj], ah, bh[nj]);
            mma16816(acc[mi][nj], al, bh[nj]);
        }
    }
}

__device__ __forceinline__ void stage_pv(uint32_t sa, uint32_t sv, int sub, int lane,
                                         int wm, int wn, float acc[4][4][4]) {
    const int lr = lane & 15;
    const uint32_t lc16 = (lane >> 4) << 4;
    const uint32_t pc16 = lc16 + (uint32_t)sub * 32;
    uint32_t bh[4][2];
#pragma unroll
    for (int j = 0; j < 2; ++j) {
        uint32_t t4[4];
        const uint32_t off = (uint32_t)(sub * 16 + lr) * VROWB +
                             (uint32_t)(wn * 32 + j * 16) * 2 + lc16;
        ldsm4t(t4, sv + off);
        bh[j*2][0] = t4[0]; bh[j*2][1] = t4[1];
        bh[j*2+1][0] = t4[2]; bh[j*2+1][1] = t4[3];
    }
#pragma unroll
    for (int mi = 0; mi < 4; ++mi) {
        uint32_t ah[4], al[4];
        const uint32_t roff = (uint32_t)(wm * 64 + mi * 16 + lr) * ROW2B + pc16;
        ldsm4(ah, sa + roff);
        ldsm4(al, sa + PLANE2 + roff);
#pragma unroll
        for (int nj = 0; nj < 4; ++nj) {
            mma16816(acc[mi][nj], ah, bh[nj]);
            mma16816(acc[mi][nj], al, bh[nj]);
        }
    }
}

#define ACC_INIT float acc[4][4][4];                                    \
    _Pragma("unroll") for (int _i = 0; _i < 4; ++_i)                    \
    _Pragma("unroll") for (int _j = 0; _j < 4; ++_j)                    \
    _Pragma("unroll") for (int _k = 0; _k < 4; ++_k) acc[_i][_j][_k] = 0.f;

// ---------------- k16 half-stage loaders (register prefetch) -----------------
struct Frag3 { uint4 v[3]; };

__device__ __forceinline__ Frag3 ld16_nt(const __half* Ah, const __half* Al,
                                         const __half* Bh,
                                         long lda, long ldb, int k0, int tid) {
    const int row = tid >> 1, half = tid & 1;
    const long ga = (long)row * lda + k0 + half * 8;
    const long gb = (long)row * ldb + k0 + half * 8;
    Frag3 f;
    f.v[0] = *(const uint4*)(Ah + ga);
    f.v[1] = *(const uint4*)(Al + ga);
    f.v[2] = *(const uint4*)(Bh + gb);
    return f;
}
__device__ __forceinline__ void st16_nt(char* dsm, int stg, int sub, Frag3 f, int tid) {
    const int row = tid >> 1, half = tid & 1;
    char* base = dsm + stg * NT_STG;
    const uint32_t so = (uint32_t)row * ROW2B + (uint32_t)sub * 32 + (uint32_t)half * 16;
    *(uint4*)(base + so)          = f.v[0];
    *(uint4*)(base + PLANE2 + so) = f.v[1];
    *(uint4*)(base + MAT2A + so)  = f.v[2];
}

__device__ __forceinline__ Frag3 ld16_pv(const __half* Ph, const __half* Pl,
                                         const __half* Vh,
                                         int n0, int k0, int tid) {
    const int row = tid >> 1, half = tid & 1;
    const long gp = (long)row * SEQ + k0 + half * 8;
    const int vr = tid >> 4, vc = (tid & 15) * 8;
    const long gv = (long)(k0 + vr) * DIM + n0 + vc;
    Frag3 f;
    f.v[0] = *(const uint4*)(Ph + gp);
    f.v[1] = *(const uint4*)(Pl + gp);
    f.v[2] = *(const uint4*)(Vh + gv);
    return f;
}
__device__ __forceinline__ void st16_pv(char* dsm, int stg, int sub, Frag3 f, int tid) {
    const int row = tid >> 1, half = tid & 1;
    char* base = dsm + stg * PV_STG;
    const uint32_t so = (uint32_t)row * ROW2B + (uint32_t)sub * 32 + (uint32_t)half * 16;
    *(uint4*)(base + so)          = f.v[0];
    *(uint4*)(base + PLANE2 + so) = f.v[1];
    const int vr = tid >> 4, vc = (tid & 15) * 8;
    const uint32_t vo = (uint32_t)(sub * 16 + vr) * VROWB + (uint32_t)vc * 2;
    *(uint4*)(base + MAT2A + vo)  = f.v[2];
}

// ---------------- kernel 0a: x -> fp16 split planes ---------------------------
__global__ __launch_bounds__(256) void cvt_x(const float* __restrict__ src) {
    const long i = ((long)blockIdx.x * 256 + threadIdx.x) * 4;
    const float4 v = *(const float4*)(src + i);
    float a[4] = { v.x, v.y, v.z, v.w };
    __half h[4], l[4];
#pragma unroll
    for (int j = 0; j < 4; ++j) split_f16(a[j], h[j], l[j]);
    *(uint2*)(g_xh + i) = *(uint2*)h;
    *(uint2*)(g_xl + i) = *(uint2*)l;
}

// ---------------- kernel 0b: Wq|Wk|Wv -> single fp16 plane --------------------
__global__ __launch_bounds__(256) void cvt_w(const float* __restrict__ wq,
                                             const float* __restrict__ wk,
                                             const float* __restrict__ wv) {
    const int mat = blockIdx.y;
    const float* src = (mat == 0) ? wq : ((mat == 1) ? wk : wv);
    const long i = ((long)blockIdx.x * 256 + threadIdx.x) * 4;
    const long o = (long)mat * DIM * DIM + i;
    const float4 v = *(const float4*)(src + i);
    __half h[4] = { __float2half_rn(v.x), __float2half_rn(v.y),
                    __float2half_rn(v.z), __float2half_rn(v.w) };
    *(uint2*)(g_wh + o) = *(uint2*)h;
}

// ---------------- NT mainloop: k32 double buffer, ONE sync per 32-k ----------
#define NT_BODY(Ah, Al, Bh, lda, ldb, NC2)                                     \
    extern __shared__ __align__(128) char dsm[];                               \
    const int tid = threadIdx.x;                                               \
    const int lane = tid & 31, wid = tid >> 5;                                 \
    const int wm = wid >> 2, wn = wid & 3;                                     \
    const uint32_t su = smem_u32(dsm);                                         \
    ACC_INIT;                                                                  \
    {                                                                          \
        Frag3 f0 = ld16_nt(Ah, Al, Bh, lda, ldb, 0, tid);                      \
        Frag3 f1 = ld16_nt(Ah, Al, Bh, lda, ldb, 16, tid);                     \
        st16_nt(dsm, 0, 0, f0, tid);                                           \
        st16_nt(dsm, 0, 1, f1, tid);                                           \
    }                                                                          \
    __syncthreads();                                                           \
    for (int c = 0; c < (NC2); ++c) {                                          \
        const int buf = c & 1;                                                 \
        const uint32_t sb0 = su + buf * NT_STG;                                \
        const bool more = (c + 1 < (NC2));                                     \
        Frag3 f;                                                               \
        if (more) f = ld16_nt(Ah, Al, Bh, lda, ldb, (c + 1) * 32, tid);        \
        stage_nt(sb0, sb0 + MAT2A, 0, lane, wm, wn, acc);                      \
        if (more) {                                                            \
            st16_nt(dsm, buf ^ 1, 0, f, tid);                                  \
            f = ld16_nt(Ah, Al, Bh, lda, ldb, (c + 1) * 32 + 16, tid);         \
        }                                                                      \
        stage_nt(sb0, sb0 + MAT2A, 1, lane, wm, wn, acc);                      \
        if (more) {                                                            \
            st16_nt(dsm, buf ^ 1, 1, f, tid);                                  \
            __syncthreads();                                                   \
        }                                                                      \
    }

// ---------------- kernel 1: QKV projection (NT) -------------------------------
__global__ __launch_bounds__(256, 2) void gemm_qkv() {
    const int m0 = blockIdx.x * 128;
    const int n0 = blockIdx.y * 128;
    NT_BODY(g_xh + (long)m0 * DIM, g_xl + (long)m0 * DIM,
            g_wh + (long)n0 * DIM, DIM, DIM, DIM / 32);

    const int mat = n0 / DIM;
    const int nl0 = n0 % DIM;
    const int r = lane >> 2, cc = (lane & 3) * 2;
    if (mat == 0) {
#pragma unroll
        for (int mi = 0; mi < 4; ++mi)
#pragma unroll
            for (int nj = 0; nj < 4; ++nj)
#pragma unroll
                for (int h2 = 0; h2 < 2; ++h2) {
                    const int m = m0 + wm * 64 + mi * 16 + r + h2 * 8;
                    const int n = nl0 + wn * 32 + nj * 8 + cc;
                    __half h0, l0, h1, l1;
                    split_f16(acc[mi][nj][h2 * 2 + 0], h0, l0);
                    split_f16(acc[mi][nj][h2 * 2 + 1], h1, l1);
                    *(__half2*)(g_qh + (long)m * DIM + n) = __halves2half2(h0, h1);
                    *(__half2*)(g_ql + (long)m * DIM + n) = __halves2half2(l0, l1);
                }
    } else {
        __half* dst = (mat == 1) ? g_kh : g_vh;
#pragma unroll
        for (int mi = 0; mi < 4; ++mi)
#pragma unroll
            for (int nj = 0; nj < 4; ++nj)
#pragma unroll
                for (int h2 = 0; h2 < 2; ++h2) {
                    const int m = m0 + wm * 64 + mi * 16 + r + h2 * 8;
                    const int n = nl0 + wn * 32 + nj * 8 + cc;
                    *(__half2*)(dst + (long)m * DIM + n) =
                        __halves2half2(__float2half_rn(acc[mi][nj][h2 * 2 + 0]),
                                       __float2half_rn(acc[mi][nj][h2 * 2 + 1]));
                }
    }
}

// ---------------- kernel 2: causal scores (NT) --------------------------------
__global__ __launch_bounds__(256, 2) void gemm_scores() {
    const int mi_t = gridDim.x - 1 - blockIdx.x;    // longest first
    if ((int)blockIdx.y > mi_t) return;             // fully above diagonal
    const int m0 = mi_t * 128, n0 = blockIdx.y * 128, b = blockIdx.z;
    NT_BODY(g_qh + ((long)b * SEQ + m0) * DIM, g_ql + ((long)b * SEQ + m0) * DIM,
            g_kh + ((long)b * SEQ + n0) * DIM, DIM, DIM, DIM / 32);

    const float scale = 0.036084391824351615f;      // 1/sqrt(768)
    float* Sg = g_S + (size_t)b * SEQ * SEQ;
    const int r = lane >> 2, cc = (lane & 3) * 2;
#pragma unroll
    for (int mi = 0; mi < 4; ++mi)
#pragma unroll
        for (int nj = 0; nj < 4; ++nj)
#pragma unroll
            for (int h2 = 0; h2 < 2; ++h2) {
                const int m = m0 + wm * 64 + mi * 16 + r + h2 * 8;
                const int n = n0 + wn * 32 + nj * 8 + cc;
                float2 v = make_float2(acc[mi][nj][h2 * 2 + 0] * scale,
                                       acc[mi][nj][h2 * 2 + 1] * scale);
                *(float2*)(Sg + (size_t)m * SEQ + n) = v;
            }
}

// ---------------- kernel 3: softmax + fp16 split P -----------------------------
__global__ __launch_bounds__(256) void softmax_kernel() {
    const int rid = blockIdx.x;
    const int q = rid & (SEQ - 1);
    float* __restrict__ row = g_S + (size_t)rid * SEQ;
    __half* __restrict__ ph = g_ph + (size_t)rid * SEQ;
    __half* __restrict__ pl = g_pl + (size_t)rid * SEQ;
    const int L = q + 1;
    const int tid = threadIdx.x;
    __shared__ float red[256];

    float m = -1e30f;
    for (int k = tid; k < L; k += 256) m = fmaxf(m, row[k]);
    red[tid] = m;
    __syncthreads();
#pragma unroll
    for (int s = 128; s > 0; s >>= 1) {
        if (tid < s) red[tid] = fmaxf(red[tid], red[tid + s]);
        __syncthreads();
    }
    m = red[0];
    __syncthreads();

    float ssum = 0.f;
    for (int k = tid; k < L; k += 256) {
        float e = __expf(row[k] - m);
        row[k] = e;
        ssum += e;
    }
    red[tid] = ssum;
    __syncthreads();
#pragma unroll
    for (int s = 128; s > 0; s >>= 1) {
        if (tid < s) red[tid] += red[tid + s];
        __syncthreads();
    }
    const float inv = 1.0f / red[0];

    for (int k = tid; k < L; k += 256) {
        __half h, l;
        split_f16(row[k] * inv, h, l);
        ph[k] = h;
        pl[k] = l;
    }
    const int kend = (q & ~127) + 128;
    const __half z = __float2half_rn(0.f);
    for (int k = L + tid; k < kend; k += 256) { ph[k] = z; pl[k] = z; }
}

// ---------------- kernel 4: O = P V --------------------------------------------
__global__ __launch_bounds__(256, 2) void gemm_pv(float* __restrict__ out) {
    const int mi_t = gridDim.x - 1 - blockIdx.x;    // longest K first
    const int m0 = mi_t * 128, n0 = blockIdx.y * 128, b = blockIdx.z;
    const __half* Ph = g_ph + ((size_t)b * SEQ + m0) * SEQ;
    const __half* Pl = g_pl + ((size_t)b * SEQ + m0) * SEQ;
    const __half* Vh = g_vh + (long)b * SEQ * DIM;

    extern __shared__ __align__(128) char dsm[];
    const int tid = threadIdx.x;
    const int lane = tid & 31, wid = tid >> 5;
    const int wm = wid >> 2, wn = wid & 3;
    const uint32_t su = smem_u32(dsm);
    ACC_INIT;
    const int NC2 = (m0 + 128) / 32;

    {
        Frag3 f0 = ld16_pv(Ph, Pl, Vh, n0, 0, tid);
        Frag3 f1 = ld16_pv(Ph, Pl, Vh, n0, 16, tid);
        st16_pv(dsm, 0, 0, f0, tid);
        st16_pv(dsm, 0, 1, f1, tid);
    }
    __syncthreads();
    for (int c = 0; c < NC2; ++c) {
        const int buf = c & 1;
        const uint32_t sb0 = su + buf * PV_STG;
        const bool more = (c + 1 < NC2);
        Frag3 f;
        if (more) f = ld16_pv(Ph, Pl, Vh, n0, (c + 1) * 32, tid);
        stage_pv(sb0, sb0 + MAT2A, 0, lane, wm, wn, acc);
        if (more) {
            st16_pv(dsm, buf ^ 1, 0, f, tid);
            f = ld16_pv(Ph, Pl, Vh, n0, (c + 1) * 32 + 16, tid);
        }
        stage_pv(sb0, sb0 + MAT2A, 1, lane, wm, wn, acc);
        if (more) {
            st16_pv(dsm, buf ^ 1, 1, f, tid);
            __syncthreads();
        }
    }

    float* Og = out + (long)b * SEQ * DIM;
    const int r = lane >> 2, cc = (lane & 3) * 2;
#pragma unroll
    for (int mi = 0; mi < 4; ++mi)
#pragma unroll
        for (int nj = 0; nj < 4; ++nj)
#pragma unroll
            for (int h2 = 0; h2 < 2; ++h2) {
                const int m = m0 + wm * 64 + mi * 16 + r + h2 * 8;
                const int n = n0 + wn * 32 + nj * 8 + cc;
                float2 v = make_float2(acc[mi][nj][h2 * 2 + 0],
                                       acc[mi][nj][h2 * 2 + 1]);
                *(float2*)(Og + (long)m * DIM + n) = v;
            }
}

// ---------------- launch ---------------------------------------------------------
extern "C" void kernel_launch(void* const* d_in, const int* in_sizes, int n_in,
                              void* d_out, int out_size) {
    const float* x  = (const float*)d_in[0];
    const float* Wq = (const float*)d_in[1];
    const float* Wk = (const float*)d_in[2];
    const float* Wv = (const float*)d_in[3];
    float* out = (float*)d_out;

    cudaFuncSetAttribute(gemm_qkv,    cudaFuncAttributeMaxDynamicSharedMemorySize, NT_SMEM);
    cudaFuncSetAttribute(gemm_scores, cudaFuncAttributeMaxDynamicSharedMemorySize, NT_SMEM);
    cudaFuncSetAttribute(gemm_pv,     cudaFuncAttributeMaxDynamicSharedMemorySize, PV_SMEM);

    cvt_x<<<(long)MROWS * DIM / 4 / 256, 256>>>(x);
    cvt_w<<<dim3(DIM * DIM / 4 / 256, 3), 256>>>(Wq, Wk, Wv);

    gemm_qkv<<<dim3(MROWS / 128, NQKV / 128), 256, NT_SMEM>>>();
    gemm_scores<<<dim3(SEQ / 128, SEQ / 128, BATCH), 256, NT_SMEM>>>();
    softmax_kernel<<<BATCH * SEQ, 256>>>();
    gemm_pv<<<dim3(SEQ / 128, DIM / 128, BATCH), 256, PV_SMEM>>>(out);
}

// round 10
// speedup vs baseline: 1.5167x; 1.5167x over previous
#include <cuda_runtime.h>
#include <cuda_fp16.h>
#include <stdint.h>

#define BATCH 4
#define SEQ   2048
#define DIM   768
#define MROWS 8192            // B*S
#define NQKV  2304            // 3*DIM

// ---------------- device scratch: fp16 planes --------------------------------
// A-side operands split (hi+lo); B-side operands single fp16 plane.
__device__ __align__(128) __half g_xh[(long)MROWS * DIM];
__device__ __align__(128) __half g_xl[(long)MROWS * DIM];
__device__ __align__(128) __half g_wh[(long)NQKV * DIM];            // W rounded
__device__ __align__(128) __half g_qh[(long)MROWS * DIM];
__device__ __align__(128) __half g_ql[(long)MROWS * DIM];
__device__ __align__(128) __half g_kh[(long)MROWS * DIM];           // K rounded
__device__ __align__(128) __half g_vh[(long)MROWS * DIM];           // V rounded, [b*S+s][d]
__device__ __align__(128) __half g_ph[(size_t)BATCH * SEQ * SEQ];
__device__ __align__(128) __half g_pl[(size_t)BATCH * SEQ * SEQ];
__device__ float g_S[(size_t)BATCH * SEQ * SEQ];

// ---------------- PTX helpers (portable, no arch-'a' features) --------------
__device__ __forceinline__ uint32_t smem_u32(const void* p) {
    uint32_t a;
    asm("{ .reg .u64 t; cvta.to.shared.u64 t, %1; cvt.u32.u64 %0, t; }"
        : "=r"(a) : "l"(p));
    return a;
}
__device__ __forceinline__ void ldsm4(uint32_t r[4], uint32_t addr) {
    asm volatile("ldmatrix.sync.aligned.m8n8.x4.shared.b16 {%0,%1,%2,%3}, [%4];"
                 : "=r"(r[0]), "=r"(r[1]), "=r"(r[2]), "=r"(r[3]) : "r"(addr));
}
__device__ __forceinline__ void ldsm4t(uint32_t r[4], uint32_t addr) {
    asm volatile("ldmatrix.sync.aligned.m8n8.x4.trans.shared.b16 {%0,%1,%2,%3}, [%4];"
                 : "=r"(r[0]), "=r"(r[1]), "=r"(r[2]), "=r"(r[3]) : "r"(addr));
}
__device__ __forceinline__ void mma16816(float d[4], const uint32_t a[4],
                                         const uint32_t b[2]) {
    asm volatile(
        "mma.sync.aligned.m16n8k16.row.col.f32.f16.f16.f32 "
        "{%0,%1,%2,%3}, {%4,%5,%6,%7}, {%8,%9}, {%0,%1,%2,%3};"
        : "+f"(d[0]), "+f"(d[1]), "+f"(d[2]), "+f"(d[3])
        : "r"(a[0]), "r"(a[1]), "r"(a[2]), "r"(a[3]), "r"(b[0]), "r"(b[1]));
}
__device__ __forceinline__ void split_f16(float v, __half& h, __half& l) {
    h = __float2half_rn(v);
    l = __float2half_rn(v - __half2float(h));
}

// ---------------- smem geometry: k32 stages, double buffered -----------------
#define ROW2B   80
#define PLANE2  10240                      // 128*80
#define MAT2A   (2 * PLANE2)               // A hi+lo = 20480
#define NT_STG  (MAT2A + PLANE2)           // A(2) + B(1) = 30720
#define NT_SMEM (2 * NT_STG)               // 61440

#define VROWB   272
#define VPLANE2 (32 * VROWB)               // 8704 (single V plane, 32 rows)
#define PV_STG  (MAT2A + VPLANE2)          // 29184
#define PV_SMEM (2 * PV_STG)               // 58368

// ---------------- stage compute: warp tile 64x64, one k16 sub-block ----------
// 4 warps (2x2): wm,wn in {0,1}. A split, B single plane. acc[4][8][4].
__device__ __forceinline__ void stage_nt(uint32_t sa, uint32_t sb, int sub, int lane,
                                         int wm, int wn, float acc[4][8][4]) {
    const int lr = lane & 15;
    const uint32_t lc16 = ((lane >> 4) << 4) + (uint32_t)sub * 32;
    uint32_t bh[8][2];
#pragma unroll
    for (int j = 0; j < 4; ++j) {
        uint32_t t4[4];
        const uint32_t roff = (uint32_t)(wn * 64 + j * 16 + lr) * ROW2B + lc16;
        ldsm4(t4, sb + roff);
        bh[j*2][0] = t4[0]; bh[j*2+1][0] = t4[1];
        bh[j*2][1] = t4[2]; bh[j*2+1][1] = t4[3];
    }
#pragma unroll
    for (int mi = 0; mi < 4; ++mi) {
        uint32_t ah[4], al[4];
        const uint32_t roff = (uint32_t)(wm * 64 + mi * 16 + lr) * ROW2B + lc16;
        ldsm4(ah, sa + roff);
        ldsm4(al, sa + PLANE2 + roff);
#pragma unroll
        for (int nj = 0; nj < 8; ++nj) {
            mma16816(acc[mi][nj], ah, bh[nj]);
            mma16816(acc[mi][nj], al, bh[nj]);
        }
    }
}

__device__ __forceinline__ void stage_pv(uint32_t sa, uint32_t sv, int sub, int lane,
                                         int wm, int wn, float acc[4][8][4]) {
    const int lr = lane & 15;
    const uint32_t lc16 = (lane >> 4) << 4;
    const uint32_t pc16 = lc16 + (uint32_t)sub * 32;
    uint32_t bh[8][2];
#pragma unroll
    for (int j = 0; j < 4; ++j) {
        uint32_t t4[4];
        const uint32_t off = (uint32_t)(sub * 16 + lr) * VROWB +
                             (uint32_t)(wn * 64 + j * 16) * 2 + lc16;
        ldsm4t(t4, sv + off);
        bh[j*2][0] = t4[0]; bh[j*2][1] = t4[1];
        bh[j*2+1][0] = t4[2]; bh[j*2+1][1] = t4[3];
    }
#pragma unroll
    for (int mi = 0; mi < 4; ++mi) {
        uint32_t ah[4], al[4];
        const uint32_t roff = (uint32_t)(wm * 64 + mi * 16 + lr) * ROW2B + pc16;
        ldsm4(ah, sa + roff);
        ldsm4(al, sa + PLANE2 + roff);
#pragma unroll
        for (int nj = 0; nj < 8; ++nj) {
            mma16816(acc[mi][nj], ah, bh[nj]);
            mma16816(acc[mi][nj], al, bh[nj]);
        }
    }
}

#define ACC_INIT float acc[4][8][4];                                    \
    _Pragma("unroll") for (int _i = 0; _i < 4; ++_i)                    \
    _Pragma("unroll") for (int _j = 0; _j < 8; ++_j)                    \
    _Pragma("unroll") for (int _k = 0; _k < 4; ++_k) acc[_i][_j][_k] = 0.f;

// ---------------- k16 half-stage loaders (128 threads, register prefetch) ----
struct Frag6 { uint4 v[6]; };

__device__ __forceinline__ Frag6 ld16_nt(const __half* Ah, const __half* Al,
                                         const __half* Bh,
                                         long lda, long ldb, int k0, int tid) {
    const long ga = (long)tid * lda + k0;
    const long gb = (long)tid * ldb + k0;
    Frag6 f;
    f.v[0] = *(const uint4*)(Ah + ga);
    f.v[1] = *(const uint4*)(Ah + ga + 8);
    f.v[2] = *(const uint4*)(Al + ga);
    f.v[3] = *(const uint4*)(Al + ga + 8);
    f.v[4] = *(const uint4*)(Bh + gb);
    f.v[5] = *(const uint4*)(Bh + gb + 8);
    return f;
}
__device__ __forceinline__ void st16_nt(char* dsm, int stg, int sub, Frag6 f, int tid) {
    char* base = dsm + stg * NT_STG;
    const uint32_t so = (uint32_t)tid * ROW2B + (uint32_t)sub * 32;
    *(uint4*)(base + so)               = f.v[0];
    *(uint4*)(base + so + 16)          = f.v[1];
    *(uint4*)(base + PLANE2 + so)      = f.v[2];
    *(uint4*)(base + PLANE2 + so + 16) = f.v[3];
    *(uint4*)(base + MAT2A + so)       = f.v[4];
    *(uint4*)(base + MAT2A + so + 16)  = f.v[5];
}

__device__ __forceinline__ Frag6 ld16_pv(const __half* Ph, const __half* Pl,
                                         const __half* Vh,
                                         int n0, int k0, int tid) {
    const long gp = (long)tid * SEQ + k0;
    const int vr = tid >> 3, vc = (tid & 7) * 16;
    const long gv = (long)(k0 + vr) * DIM + n0 + vc;
    Frag6 f;
    f.v[0] = *(const uint4*)(Ph + gp);
    f.v[1] = *(const uint4*)(Ph + gp + 8);
    f.v[2] = *(const uint4*)(Pl + gp);
    f.v[3] = *(const uint4*)(Pl + gp + 8);
    f.v[4] = *(const uint4*)(Vh + gv);
    f.v[5] = *(const uint4*)(Vh + gv + 8);
    return f;
}
__device__ __forceinline__ void st16_pv(char* dsm, int stg, int sub, Frag6 f, int tid) {
    char* base = dsm + stg * PV_STG;
    const uint32_t so = (uint32_t)tid * ROW2B + (uint32_t)sub * 32;
    *(uint4*)(base + so)               = f.v[0];
    *(uint4*)(base + so + 16)          = f.v[1];
    *(uint4*)(base + PLANE2 + so)      = f.v[2];
    *(uint4*)(base + PLANE2 + so + 16) = f.v[3];
    const int vr = tid >> 3, vc = (tid & 7) * 16;
    const uint32_t vo = (uint32_t)(sub * 16 + vr) * VROWB + (uint32_t)vc * 2;
    *(uint4*)(base + MAT2A + vo)      = f.v[4];
    *(uint4*)(base + MAT2A + vo + 16) = f.v[5];
}

// ---------------- kernel 0a: x -> fp16 split planes ---------------------------
__global__ __launch_bounds__(256) void cvt_x(const float* __restrict__ src) {
    const long i = ((long)blockIdx.x * 256 + threadIdx.x) * 4;
    const float4 v = *(const float4*)(src + i);
    float a[4] = { v.x, v.y, v.z, v.w };
    __half h[4], l[4];
#pragma unroll
    for (int j = 0; j < 4; ++j) split_f16(a[j], h[j], l[j]);
    *(uint2*)(g_xh + i) = *(uint2*)h;
    *(uint2*)(g_xl + i) = *(uint2*)l;
}

// ---------------- kernel 0b: Wq|Wk|Wv -> single fp16 plane --------------------
__global__ __launch_bounds__(256) void cvt_w(const float* __restrict__ wq,
                                             const float* __restrict__ wk,
                                             const float* __restrict__ wv) {
    const int mat = blockIdx.y;
    const float* src = (mat == 0) ? wq : ((mat == 1) ? wk : wv);
    const long i = ((long)blockIdx.x * 256 + threadIdx.x) * 4;
    const long o = (long)mat * DIM * DIM + i;
    const float4 v = *(const float4*)(src + i);
    __half h[4] = { __float2half_rn(v.x), __float2half_rn(v.y),
                    __float2half_rn(v.z), __float2half_rn(v.w) };
    *(uint2*)(g_wh + o) = *(uint2*)h;
}

// ---------------- NT mainloop: k32 double buffer, ONE sync per 32-k ----------
#define NT_BODY(Ah, Al, Bh, lda, ldb, NC2)                                     \
    extern __shared__ __align__(128) char dsm[];                               \
    const int tid = threadIdx.x;                                               \
    const int lane = tid & 31, wid = tid >> 5;                                 \
    const int wm = wid >> 1, wn = wid & 1;                                     \
    const uint32_t su = smem_u32(dsm);                                         \
    ACC_INIT;                                                                  \
    {                                                                          \
        Frag6 f0 = ld16_nt(Ah, Al, Bh, lda, ldb, 0, tid);                      \
        Frag6 f1 = ld16_nt(Ah, Al, Bh, lda, ldb, 16, tid);                     \
        st16_nt(dsm, 0, 0, f0, tid);                                           \
        st16_nt(dsm, 0, 1, f1, tid);                                           \
    }                                                                          \
    __syncthreads();                                                           \
    for (int c = 0; c < (NC2); ++c) {                                          \
        const int buf = c & 1;                                                 \
        const uint32_t sb0 = su + buf * NT_STG;                                \
        const bool more = (c + 1 < (NC2));                                     \
        Frag6 f;                                                               \
        if (more) f = ld16_nt(Ah, Al, Bh, lda, ldb, (c + 1) * 32, tid);        \
        stage_nt(sb0, sb0 + MAT2A, 0, lane, wm, wn, acc);                      \
        if (more) {                                                            \
            st16_nt(dsm, buf ^ 1, 0, f, tid);                                  \
            f = ld16_nt(Ah, Al, Bh, lda, ldb, (c + 1) * 32 + 16, tid);         \
        }                                                                      \
        stage_nt(sb0, sb0 + MAT2A, 1, lane, wm, wn, acc);                      \
        if (more) {                                                            \
            st16_nt(dsm, buf ^ 1, 1, f, tid);                                  \
            __syncthreads();                                                   \
        }                                                                      \
    }

// ---------------- kernel 1: QKV projection (NT) -------------------------------
__global__ __launch_bounds__(128, 2) void gemm_qkv() {
    const int m0 = blockIdx.x * 128;
    const int n0 = blockIdx.y * 128;
    NT_BODY(g_xh + (long)m0 * DIM, g_xl + (long)m0 * DIM,
            g_wh + (long)n0 * DIM, DIM, DIM, DIM / 32);

    const int mat = n0 / DIM;
    const int nl0 = n0 % DIM;
    const int r = lane >> 2, cc = (lane & 3) * 2;
    if (mat == 0) {
#pragma unroll
        for (int mi = 0; mi < 4; ++mi)
#pragma unroll
            for (int nj = 0; nj < 8; ++nj)
#pragma unroll
                for (int h2 = 0; h2 < 2; ++h2) {
                    const int m = m0 + wm * 64 + mi * 16 + r + h2 * 8;
                    const int n = nl0 + wn * 64 + nj * 8 + cc;
                    __half h0, l0, h1, l1;
                    split_f16(acc[mi][nj][h2 * 2 + 0], h0, l0);
                    split_f16(acc[mi][nj][h2 * 2 + 1], h1, l1);
                    *(__half2*)(g_qh + (long)m * DIM + n) = __halves2half2(h0, h1);
                    *(__half2*)(g_ql + (long)m * DIM + n) = __halves2half2(l0, l1);
                }
    } else {
        __half* dst = (mat == 1) ? g_kh : g_vh;
#pragma unroll
        for (int mi = 0; mi < 4; ++mi)
#pragma unroll
            for (int nj = 0; nj < 8; ++nj)
#pragma unroll
                for (int h2 = 0; h2 < 2; ++h2) {
                    const int m = m0 + wm * 64 + mi * 16 + r + h2 * 8;
                    const int n = nl0 + wn * 64 + nj * 8 + cc;
                    *(__half2*)(dst + (long)m * DIM + n) =
                        __halves2half2(__float2half_rn(acc[mi][nj][h2 * 2 + 0]),
                                       __float2half_rn(acc[mi][nj][h2 * 2 + 1]));
                }
    }
}

// ---------------- kernel 2: causal scores (NT) --------------------------------
__global__ __launch_bounds__(128, 2) void gemm_scores() {
    const int mi_t = gridDim.x - 1 - blockIdx.x;    // longest first
    if ((int)blockIdx.y > mi_t) return;             // fully above diagonal
    const int m0 = mi_t * 128, n0 = blockIdx.y * 128, b = blockIdx.z;
    NT_BODY(g_qh + ((long)b * SEQ + m0) * DIM, g_ql + ((long)b * SEQ + m0) * DIM,
            g_kh + ((long)b * SEQ + n0) * DIM, DIM, DIM, DIM / 32);

    const float scale = 0.036084391824351615f;      // 1/sqrt(768)
    float* Sg = g_S + (size_t)b * SEQ * SEQ;
    const int r = lane >> 2, cc = (lane & 3) * 2;
#pragma unroll
    for (int mi = 0; mi < 4; ++mi)
#pragma unroll
        for (int nj = 0; nj < 8; ++nj)
#pragma unroll
            for (int h2 = 0; h2 < 2; ++h2) {
                const int m = m0 + wm * 64 + mi * 16 + r + h2 * 8;
                const int n = n0 + wn * 64 + nj * 8 + cc;
                float2 v = make_float2(acc[mi][nj][h2 * 2 + 0] * scale,
                                       acc[mi][nj][h2 * 2 + 1] * scale);
                *(float2*)(Sg + (size_t)m * SEQ + n) = v;
            }
}

// ---------------- kernel 3: softmax + fp16 split P -----------------------------
__global__ __launch_bounds__(256) void softmax_kernel() {
    const int rid = blockIdx.x;
    const int q = rid & (SEQ - 1);
    float* __restrict__ row = g_S + (size_t)rid * SEQ;
    __half* __restrict__ ph = g_ph + (size_t)rid * SEQ;
    __half* __restrict__ pl = g_pl + (size_t)rid * SEQ;
    const int L = q + 1;
    const int tid = threadIdx.x;
    __shared__ float red[256];

    float m = -1e30f;
    for (int k = tid; k < L; k += 256) m = fmaxf(m, row[k]);
    red[tid] = m;
    __syncthreads();
#pragma unroll
    for (int s = 128; s > 0; s >>= 1) {
        if (tid < s) red[tid] = fmaxf(red[tid], red[tid + s]);
        __syncthreads();
    }
    m = red[0];
    __syncthreads();

    float ssum = 0.f;
    for (int k = tid; k < L; k += 256) {
        float e = __expf(row[k] - m);
        row[k] = e;
        ssum += e;
    }
    red[tid] = ssum;
    __syncthreads();
#pragma unroll
    for (int s = 128; s > 0; s >>= 1) {
        if (tid < s) red[tid] += red[tid + s];
        __syncthreads();
    }
    const float inv = 1.0f / red[0];

    for (int k = tid; k < L; k += 256) {
        __half h, l;
        split_f16(row[k] * inv, h, l);
        ph[k] = h;
        pl[k] = l;
    }
    const int kend = (q & ~127) + 128;
    const __half z = __float2half_rn(0.f);
    for (int k = L + tid; k < kend; k += 256) { ph[k] = z; pl[k] = z; }
}

// ---------------- kernel 4: O = P V --------------------------------------------
__global__ __launch_bounds__(128, 2) void gemm_pv(float* __restrict__ out) {
    const int mi_t = gridDim.x - 1 - blockIdx.x;    // longest K first
    const int m0 = mi_t * 128, n0 = blockIdx.y * 128, b = blockIdx.z;
    const __half* Ph = g_ph + ((size_t)b * SEQ + m0) * SEQ;
    const __half* Pl = g_pl + ((size_t)b * SEQ + m0) * SEQ;
    const __half* Vh = g_vh + (long)b * SEQ * DIM;

    extern __shared__ __align__(128) char dsm[];
    const int tid = threadIdx.x;
    const int lane = tid & 31, wid = tid >> 5;
    const int wm = wid >> 1, wn = wid & 1;
    const uint32_t su = smem_u32(dsm);
    ACC_INIT;
    const int NC2 = (m0 + 128) / 32;

    {
        Frag6 f0 = ld16_pv(Ph, Pl, Vh, n0, 0, tid);
        Frag6 f1 = ld16_pv(Ph, Pl, Vh, n0, 16, tid);
        st16_pv(dsm, 0, 0, f0, tid);
        st16_pv(dsm, 0, 1, f1, tid);
    }
    __syncthreads();
    for (int c = 0; c < NC2; ++c) {
        const int buf = c & 1;
        const uint32_t sb0 = su + buf * PV_STG;
        const bool more = (c + 1 < NC2);
        Frag6 f;
        if (more) f = ld16_pv(Ph, Pl, Vh, n0, (c + 1) * 32, tid);
        stage_pv(sb0, sb0 + MAT2A, 0, lane, wm, wn, acc);
        if (more) {
            st16_pv(dsm, buf ^ 1, 0, f, tid);
            f = ld16_pv(Ph, Pl, Vh, n0, (c + 1) * 32 + 16, tid);
        }
        stage_pv(sb0, sb0 + MAT2A, 1, lane, wm, wn, acc);
        if (more) {
            st16_pv(dsm, buf ^ 1, 1, f, tid);
            __syncthreads();
        }
    }

    float* Og = out + (long)b * SEQ * DIM;
    const int r = lane >> 2, cc = (lane & 3) * 2;
#pragma unroll
    for (int mi = 0; mi < 4; ++mi)
#pragma unroll
        for (int nj = 0; nj < 8; ++nj)
#pragma unroll
            for (int h2 = 0; h2 < 2; ++h2) {
                const int m = m0 + wm * 64 + mi * 16 + r + h2 * 8;
                const int n = n0 + wn * 64 + nj * 8 + cc;
                float2 v = make_float2(acc[mi][nj][h2 * 2 + 0],
                                       acc[mi][nj][h2 * 2 + 1]);
                *(float2*)(Og + (long)m * DIM + n) = v;
            }
}

// ---------------- launch ---------------------------------------------------------
extern "C" void kernel_launch(void* const* d_in, const int* in_sizes, int n_in,
                              void* d_out, int out_size) {
    const float* x  = (const float*)d_in[0];
    const float* Wq = (const float*)d_in[1];
    const float* Wk = (const float*)d_in[2];
    const float* Wv = (const float*)d_in[3];
    float* out = (float*)d_out;

    cudaFuncSetAttribute(gemm_qkv,    cudaFuncAttributeMaxDynamicSharedMemorySize, NT_SMEM);
    cudaFuncSetAttribute(gemm_scores, cudaFuncAttributeMaxDynamicSharedMemorySize, NT_SMEM);
    cudaFuncSetAttribute(gemm_pv,     cudaFuncAttributeMaxDynamicSharedMemorySize, PV_SMEM);

    cvt_x<<<(long)MROWS * DIM / 4 / 256, 256>>>(x);
    cvt_w<<<dim3(DIM * DIM / 4 / 256, 3), 256>>>(Wq, Wk, Wv);

    gemm_qkv<<<dim3(MROWS / 128, NQKV / 128), 128, NT_SMEM>>>();
    gemm_scores<<<dim3(SEQ / 128, SEQ / 128, BATCH), 128, NT_SMEM>>>();
    softmax_kernel<<<BATCH * SEQ, 256>>>();
    gemm_pv<<<dim3(SEQ / 128, DIM / 128, BATCH), 128, PV_SMEM>>>(out);
}

// round 11
// speedup vs baseline: 1.5213x; 1.0030x over previous
#include <cuda_runtime.h>
#include <cuda_fp16.h>
#include <stdint.h>

#define BATCH 4
#define SEQ   2048
#define DIM   768
#define MROWS 8192            // B*S
#define NQKV  2304            // 3*DIM

// ---------------- device scratch: fp16 planes --------------------------------
// A-side operands split (hi+lo); B-side operands single fp16 plane.
__device__ __align__(128) __half g_xh[(long)MROWS * DIM];
__device__ __align__(128) __half g_xl[(long)MROWS * DIM];
__device__ __align__(128) __half g_wh[(long)NQKV * DIM];            // W rounded
__device__ __align__(128) __half g_qh[(long)MROWS * DIM];
__device__ __align__(128) __half g_ql[(long)MROWS * DIM];
__device__ __align__(128) __half g_kh[(long)MROWS * DIM];           // K rounded
__device__ __align__(128) __half g_vh[(long)MROWS * DIM];           // V rounded, [b*S+s][d]
__device__ __align__(128) __half g_ph[(size_t)BATCH * SEQ * SEQ];
__device__ __align__(128) __half g_pl[(size_t)BATCH * SEQ * SEQ];
__device__ float g_S[(size_t)BATCH * SEQ * SEQ];

// ---------------- PTX helpers (portable, no arch-'a' features) --------------
__device__ __forceinline__ uint32_t smem_u32(const void* p) {
    uint32_t a;
    asm("{ .reg .u64 t; cvta.to.shared.u64 t, %1; cvt.u32.u64 %0, t; }"
        : "=r"(a) : "l"(p));
    return a;
}
__device__ __forceinline__ void ldsm4(uint32_t r[4], uint32_t addr) {
    asm volatile("ldmatrix.sync.aligned.m8n8.x4.shared.b16 {%0,%1,%2,%3}, [%4];"
                 : "=r"(r[0]), "=r"(r[1]), "=r"(r[2]), "=r"(r[3]) : "r"(addr));
}
__device__ __forceinline__ void ldsm4t(uint32_t r[4], uint32_t addr) {
    asm volatile("ldmatrix.sync.aligned.m8n8.x4.trans.shared.b16 {%0,%1,%2,%3}, [%4];"
                 : "=r"(r[0]), "=r"(r[1]), "=r"(r[2]), "=r"(r[3]) : "r"(addr));
}
__device__ __forceinline__ void mma16816(float d[4], const uint32_t a[4],
                                         const uint32_t b[2]) {
    asm volatile(
        "mma.sync.aligned.m16n8k16.row.col.f32.f16.f16.f32 "
        "{%0,%1,%2,%3}, {%4,%5,%6,%7}, {%8,%9}, {%0,%1,%2,%3};"
        : "+f"(d[0]), "+f"(d[1]), "+f"(d[2]), "+f"(d[3])
        : "r"(a[0]), "r"(a[1]), "r"(a[2]), "r"(a[3]), "r"(b[0]), "r"(b[1]));
}
__device__ __forceinline__ void split_f16(float v, __half& h, __half& l) {
    h = __float2half_rn(v);
    l = __float2half_rn(v - __half2float(h));
}

// ---------------- smem geometry: k32 stages, double buffered -----------------
#define ROW2B   80
#define PLANE2  10240                      // 128*80
#define MAT2A   (2 * PLANE2)               // A hi+lo = 20480
#define NT_STG  (MAT2A + PLANE2)           // A(2) + B(1) = 30720
#define NT_SMEM (2 * NT_STG)               // 61440

#define VROWB   272
#define VPLANE2 (32 * VROWB)               // 8704 (single V plane, 32 rows)
#define PV_STG  (MAT2A + VPLANE2)          // 29184
#define PV_SMEM (2 * PV_STG)               // 58368

// ---------------- stage compute: warp tile 64x64, one k16 sub-block ----------
// 4 warps (2x2). A fragments double-buffered in registers: the ldsm pair for
// mi+1 issues BEFORE the 16 MMAs of mi, hiding LDSM latency at 8 warps/SM.
__device__ __forceinline__ void stage_nt(uint32_t sa, uint32_t sb, int sub, int lane,
                                         int wm, int wn, float acc[4][8][4]) {
    const int lr = lane & 15;
    const uint32_t lc16 = ((lane >> 4) << 4) + (uint32_t)sub * 32;
    uint32_t bh[8][2];
#pragma unroll
    for (int j = 0; j < 4; ++j) {
        uint32_t t4[4];
        const uint32_t roff = (uint32_t)(wn * 64 + j * 16 + lr) * ROW2B + lc16;
        ldsm4(t4, sb + roff);
        bh[j*2][0] = t4[0]; bh[j*2+1][0] = t4[1];
        bh[j*2][1] = t4[2]; bh[j*2+1][1] = t4[3];
    }
    const uint32_t abase = (uint32_t)(wm * 64 + lr) * ROW2B + lc16;
    uint32_t ah[2][4], al[2][4];
    ldsm4(ah[0], sa + abase);
    ldsm4(al[0], sa + PLANE2 + abase);
#pragma unroll
    for (int mi = 0; mi < 4; ++mi) {
        if (mi < 3) {
            const uint32_t roff = abase + (uint32_t)((mi + 1) * 16) * ROW2B;
            ldsm4(ah[(mi + 1) & 1], sa + roff);
            ldsm4(al[(mi + 1) & 1], sa + PLANE2 + roff);
        }
        const uint32_t* a_h = ah[mi & 1];
        const uint32_t* a_l = al[mi & 1];
#pragma unroll
        for (int nj = 0; nj < 8; ++nj) {
            mma16816(acc[mi][nj], a_h, bh[nj]);
            mma16816(acc[mi][nj], a_l, bh[nj]);
        }
    }
}

__device__ __forceinline__ void stage_pv(uint32_t sa, uint32_t sv, int sub, int lane,
                                         int wm, int wn, float acc[4][8][4]) {
    const int lr = lane & 15;
    const uint32_t lc16 = (lane >> 4) << 4;
    const uint32_t pc16 = lc16 + (uint32_t)sub * 32;
    uint32_t bh[8][2];
#pragma unroll
    for (int j = 0; j < 4; ++j) {
        uint32_t t4[4];
        const uint32_t off = (uint32_t)(sub * 16 + lr) * VROWB +
                             (uint32_t)(wn * 64 + j * 16) * 2 + lc16;
        ldsm4t(t4, sv + off);
        bh[j*2][0] = t4[0]; bh[j*2][1] = t4[1];
        bh[j*2+1][0] = t4[2]; bh[j*2+1][1] = t4[3];
    }
    const uint32_t abase = (uint32_t)(wm * 64 + lr) * ROW2B + pc16;
    uint32_t ah[2][4], al[2][4];
    ldsm4(ah[0], sa + abase);
    ldsm4(al[0], sa + PLANE2 + abase);
#pragma unroll
    for (int mi = 0; mi < 4; ++mi) {
        if (mi < 3) {
            const uint32_t roff = abase + (uint32_t)((mi + 1) * 16) * ROW2B;
            ldsm4(ah[(mi + 1) & 1], sa + roff);
            ldsm4(al[(mi + 1) & 1], sa + PLANE2 + roff);
        }
        const uint32_t* a_h = ah[mi & 1];
        const uint32_t* a_l = al[mi & 1];
#pragma unroll
        for (int nj = 0; nj < 8; ++nj) {
            mma16816(acc[mi][nj], a_h, bh[nj]);
            mma16816(acc[mi][nj], a_l, bh[nj]);
        }
    }
}

#define ACC_INIT float acc[4][8][4];                                    \
    _Pragma("unroll") for (int _i = 0; _i < 4; ++_i)                    \
    _Pragma("unroll") for (int _j = 0; _j < 8; ++_j)                    \
    _Pragma("unroll") for (int _k = 0; _k < 4; ++_k) acc[_i][_j][_k] = 0.f;

// ---------------- k16 half-stage loaders (128 threads, register prefetch) ----
struct Frag6 { uint4 v[6]; };

__device__ __forceinline__ Frag6 ld16_nt(const __half* Ah, const __half* Al,
                                         const __half* Bh,
                                         long lda, long ldb, int k0, int tid) {
    const long ga = (long)tid * lda + k0;
    const long gb = (long)tid * ldb + k0;
    Frag6 f;
    f.v[0] = *(const uint4*)(Ah + ga);
    f.v[1] = *(const uint4*)(Ah + ga + 8);
    f.v[2] = *(const uint4*)(Al + ga);
    f.v[3] = *(const uint4*)(Al + ga + 8);
    f.v[4] = *(const uint4*)(Bh + gb);
    f.v[5] = *(const uint4*)(Bh + gb + 8);
    return f;
}
__device__ __forceinline__ void st16_nt(char* dsm, int stg, int sub, Frag6 f, int tid) {
    char* base = dsm + stg * NT_STG;
    const uint32_t so = (uint32_t)tid * ROW2B + (uint32_t)sub * 32;
    *(uint4*)(base + so)               = f.v[0];
    *(uint4*)(base + so + 16)          = f.v[1];
    *(uint4*)(base + PLANE2 + so)      = f.v[2];
    *(uint4*)(base + PLANE2 + so + 16) = f.v[3];
    *(uint4*)(base + MAT2A + so)       = f.v[4];
    *(uint4*)(base + MAT2A + so + 16)  = f.v[5];
}

__device__ __forceinline__ Frag6 ld16_pv(const __half* Ph, const __half* Pl,
                                         const __half* Vh,
                                         int n0, int k0, int tid) {
    const long gp = (long)tid * SEQ + k0;
    const int vr = tid >> 3, vc = (tid & 7) * 16;
    const long gv = (long)(k0 + vr) * DIM + n0 + vc;
    Frag6 f;
    f.v[0] = *(const uint4*)(Ph + gp);
    f.v[1] = *(const uint4*)(Ph + gp + 8);
    f.v[2] = *(const uint4*)(Pl + gp);
    f.v[3] = *(const uint4*)(Pl + gp + 8);
    f.v[4] = *(const uint4*)(Vh + gv);
    f.v[5] = *(const uint4*)(Vh + gv + 8);
    return f;
}
__device__ __forceinline__ void st16_pv(char* dsm, int stg, int sub, Frag6 f, int tid) {
    char* base = dsm + stg * PV_STG;
    const uint32_t so = (uint32_t)tid * ROW2B + (uint32_t)sub * 32;
    *(uint4*)(base + so)               = f.v[0];
    *(uint4*)(base + so + 16)          = f.v[1];
    *(uint4*)(base + PLANE2 + so)      = f.v[2];
    *(uint4*)(base + PLANE2 + so + 16) = f.v[3];
    const int vr = tid >> 3, vc = (tid & 7) * 16;
    const uint32_t vo = (uint32_t)(sub * 16 + vr) * VROWB + (uint32_t)vc * 2;
    *(uint4*)(base + MAT2A + vo)      = f.v[4];
    *(uint4*)(base + MAT2A + vo + 16) = f.v[5];
}

// ---------------- kernel 0a: x -> fp16 split planes ---------------------------
__global__ __launch_bounds__(256) void cvt_x(const float* __restrict__ src) {
    const long i = ((long)blockIdx.x * 256 + threadIdx.x) * 4;
    const float4 v = *(const float4*)(src + i);
    float a[4] = { v.x, v.y, v.z, v.w };
    __half h[4], l[4];
#pragma unroll
    for (int j = 0; j < 4; ++j) split_f16(a[j], h[j], l[j]);
    *(uint2*)(g_xh + i) = *(uint2*)h;
    *(uint2*)(g_xl + i) = *(uint2*)l;
}

// ---------------- kernel 0b: Wq|Wk|Wv -> single fp16 plane --------------------
__global__ __launch_bounds__(256) void cvt_w(const float* __restrict__ wq,
                                             const float* __restrict__ wk,
                                             const float* __restrict__ wv) {
    const int mat = blockIdx.y;
    const float* src = (mat == 0) ? wq : ((mat == 1) ? wk : wv);
    const long i = ((long)blockIdx.x * 256 + threadIdx.x) * 4;
    const long o = (long)mat * DIM * DIM + i;
    const float4 v = *(const float4*)(src + i);
    __half h[4] = { __float2half_rn(v.x), __float2half_rn(v.y),
                    __float2half_rn(v.z), __float2half_rn(v.w) };
    *(uint2*)(g_wh + o) = *(uint2*)h;
}

// ---------------- NT mainloop: k32 double buffer, ONE sync per 32-k ----------
#define NT_BODY(Ah, Al, Bh, lda, ldb, NC2)                                     \
    extern __shared__ __align__(128) char dsm[];                               \
    const int tid = threadIdx.x;                                               \
    const int lane = tid & 31, wid = tid >> 5;                                 \
    const int wm = wid >> 1, wn = wid & 1;                                     \
    const uint32_t su = smem_u32(dsm);                                         \
    ACC_INIT;                                                                  \
    {                                                                          \
        Frag6 f0 = ld16_nt(Ah, Al, Bh, lda, ldb, 0, tid);                      \
        Frag6 f1 = ld16_nt(Ah, Al, Bh, lda, ldb, 16, tid);                     \
        st16_nt(dsm, 0, 0, f0, tid);                                           \
        st16_nt(dsm, 0, 1, f1, tid);                                           \
    }                                                                          \
    __syncthreads();                                                           \
    for (int c = 0; c < (NC2); ++c) {                                          \
        const int buf = c & 1;                                                 \
        const uint32_t sb0 = su + buf * NT_STG;                                \
        const bool more = (c + 1 < (NC2));                                     \
        Frag6 f;                                                               \
        if (more) f = ld16_nt(Ah, Al, Bh, lda, ldb, (c + 1) * 32, tid);        \
        stage_nt(sb0, sb0 + MAT2A, 0, lane, wm, wn, acc);                      \
        if (more) {                                                            \
            st16_nt(dsm, buf ^ 1, 0, f, tid);                                  \
            f = ld16_nt(Ah, Al, Bh, lda, ldb, (c + 1) * 32 + 16, tid);         \
        }                                                                      \
        stage_nt(sb0, sb0 + MAT2A, 1, lane, wm, wn, acc);                      \
        if (more) {                                                            \
            st16_nt(dsm, buf ^ 1, 1, f, tid);                                  \
            __syncthreads();                                                   \
        }                                                                      \
    }

// ---------------- kernel 1: QKV projection (NT) -------------------------------
__global__ __launch_bounds__(128, 2) void gemm_qkv() {
    const int m0 = blockIdx.x * 128;
    const int n0 = blockIdx.y * 128;
    NT_BODY(g_xh + (long)m0 * DIM, g_xl + (long)m0 * DIM,
            g_wh + (long)n0 * DIM, DIM, DIM, DIM / 32);

    const int mat = n0 / DIM;
    const int nl0 = n0 % DIM;
    const int r = lane >> 2, cc = (lane & 3) * 2;
    if (mat == 0) {
#pragma unroll
        for (int mi = 0; mi < 4; ++mi)
#pragma unroll
            for (int nj = 0; nj < 8; ++nj)
#pragma unroll
                for (int h2 = 0; h2 < 2; ++h2) {
                    const int m = m0 + wm * 64 + mi * 16 + r + h2 * 8;
                    const int n = nl0 + wn * 64 + nj * 8 + cc;
                    __half h0, l0, h1, l1;
                    split_f16(acc[mi][nj][h2 * 2 + 0], h0, l0);
                    split_f16(acc[mi][nj][h2 * 2 + 1], h1, l1);
                    *(__half2*)(g_qh + (long)m * DIM + n) = __halves2half2(h0, h1);
                    *(__half2*)(g_ql + (long)m * DIM + n) = __halves2half2(l0, l1);
                }
    } else {
        __half* dst = (mat == 1) ? g_kh : g_vh;
#pragma unroll
        for (int mi = 0; mi < 4; ++mi)
#pragma unroll
            for (int nj = 0; nj < 8; ++nj)
#pragma unroll
                for (int h2 = 0; h2 < 2; ++h2) {
                    const int m = m0 + wm * 64 + mi * 16 + r + h2 * 8;
                    const int n = nl0 + wn * 64 + nj * 8 + cc;
                    *(__half2*)(dst + (long)m * DIM + n) =
                        __halves2half2(__float2half_rn(acc[mi][nj][h2 * 2 + 0]),
                                       __float2half_rn(acc[mi][nj][h2 * 2 + 1]));
                }
    }
}

// ---------------- kernel 2: causal scores (NT) --------------------------------
__global__ __launch_bounds__(128, 2) void gemm_scores() {
    const int mi_t = gridDim.x - 1 - blockIdx.x;    // longest first
    if ((int)blockIdx.y > mi_t) return;             // fully above diagonal
    const int m0 = mi_t * 128, n0 = blockIdx.y * 128, b = blockIdx.z;
    NT_BODY(g_qh + ((long)b * SEQ + m0) * DIM, g_ql + ((long)b * SEQ + m0) * DIM,
            g_kh + ((long)b * SEQ + n0) * DIM, DIM, DIM, DIM / 32);

    const float scale = 0.036084391824351615f;      // 1/sqrt(768)
    float* Sg = g_S + (size_t)b * SEQ * SEQ;
    const int r = lane >> 2, cc = (lane & 3) * 2;
#pragma unroll
    for (int mi = 0; mi < 4; ++mi)
#pragma unroll
        for (int nj = 0; nj < 8; ++nj)
#pragma unroll
            for (int h2 = 0; h2 < 2; ++h2) {
                const int m = m0 + wm * 64 + mi * 16 + r + h2 * 8;
                const int n = n0 + wn * 64 + nj * 8 + cc;
                float2 v = make_float2(acc[mi][nj][h2 * 2 + 0] * scale,
                                       acc[mi][nj][h2 * 2 + 1] * scale);
                *(float2*)(Sg + (size_t)m * SEQ + n) = v;
            }
}

// ---------------- kernel 3: softmax + fp16 split P -----------------------------
__global__ __launch_bounds__(256) void softmax_kernel() {
    const int rid = blockIdx.x;
    const int q = rid & (SEQ - 1);
    float* __restrict__ row = g_S + (size_t)rid * SEQ;
    __half* __restrict__ ph = g_ph + (size_t)rid * SEQ;
    __half* __restrict__ pl = g_pl + (size_t)rid * SEQ;
    const int L = q + 1;
    const int tid = threadIdx.x;
    __shared__ float red[256];

    float m = -1e30f;
    for (int k = tid; k < L; k += 256) m = fmaxf(m, row[k]);
    red[tid] = m;
    __syncthreads();
#pragma unroll
    for (int s = 128; s > 0; s >>= 1) {
        if (tid < s) red[tid] = fmaxf(red[tid], red[tid + s]);
        __syncthreads();
    }
    m = red[0];
    __syncthreads();

    float ssum = 0.f;
    for (int k = tid; k < L; k += 256) {
        float e = __expf(row[k] - m);
        row[k] = e;
        ssum += e;
    }
    red[tid] = ssum;
    __syncthreads();
#pragma unroll
    for (int s = 128; s > 0; s >>= 1) {
        if (tid < s) red[tid] += red[tid + s];
        __syncthreads();
    }
    const float inv = 1.0f / red[0];

    for (int k = tid; k < L; k += 256) {
        __half h, l;
        split_f16(row[k] * inv, h, l);
        ph[k] = h;
        pl[k] = l;
    }
    const int kend = (q & ~127) + 128;
    const __half z = __float2half_rn(0.f);
    for (int k = L + tid; k < kend; k += 256) { ph[k] = z; pl[k] = z; }
}

// ---------------- kernel 4: O = P V --------------------------------------------
__global__ __launch_bounds__(128, 2) void gemm_pv(float* __restrict__ out) {
    const int mi_t = gridDim.x - 1 - blockIdx.x;    // longest K first
    const int m0 = mi_t * 128, n0 = blockIdx.y * 128, b = blockIdx.z;
    const __half* Ph = g_ph + ((size_t)b * SEQ + m0) * SEQ;
    const __half* Pl = g_pl + ((size_t)b * SEQ + m0) * SEQ;
    const __half* Vh = g_vh + (long)b * SEQ * DIM;

    extern __shared__ __align__(128) char dsm[];
    const int tid = threadIdx.x;
    const int lane = tid & 31, wid = tid >> 5;
    const int wm = wid >> 1, wn = wid & 1;
    const uint32_t su = smem_u32(dsm);
    ACC_INIT;
    const int NC2 = (m0 + 128) / 32;

    {
        Frag6 f0 = ld16_pv(Ph, Pl, Vh, n0, 0, tid);
        Frag6 f1 = ld16_pv(Ph, Pl, Vh, n0, 16, tid);
        st16_pv(dsm, 0, 0, f0, tid);
        st16_pv(dsm, 0, 1, f1, tid);
    }
    __syncthreads();
    for (int c = 0; c < NC2; ++c) {
        const int buf = c & 1;
        const uint32_t sb0 = su + buf * PV_STG;
        const bool more = (c + 1 < NC2);
        Frag6 f;
        if (more) f = ld16_pv(Ph, Pl, Vh, n0, (c + 1) * 32, tid);
        stage_pv(sb0, sb0 + MAT2A, 0, lane, wm, wn, acc);
        if (more) {
            st16_pv(dsm, buf ^ 1, 0, f, tid);
            f = ld16_pv(Ph, Pl, Vh, n0, (c + 1) * 32 + 16, tid);
        }
        stage_pv(sb0, sb0 + MAT2A, 1, lane, wm, wn, acc);
        if (more) {
            st16_pv(dsm, buf ^ 1, 1, f, tid);
            __syncthreads();
        }
    }

    float* Og = out + (long)b * SEQ * DIM;
    const int r = lane >> 2, cc = (lane & 3) * 2;
#pragma unroll
    for (int mi = 0; mi < 4; ++mi)
#pragma unroll
        for (int nj = 0; nj < 8; ++nj)
#pragma unroll
            for (int h2 = 0; h2 < 2; ++h2) {
                const int m = m0 + wm * 64 + mi * 16 + r + h2 * 8;
                const int n = n0 + wn * 64 + nj * 8 + cc;
                float2 v = make_float2(acc[mi][nj][h2 * 2 + 0],
                                       acc[mi][nj][h2 * 2 + 1]);
                *(float2*)(Og + (long)m * DIM + n) = v;
            }
}

// ---------------- launch ---------------------------------------------------------
extern "C" void kernel_launch(void* const* d_in, const int* in_sizes, int n_in,
                              void* d_out, int out_size) {
    const float* x  = (const float*)d_in[0];
    const float* Wq = (const float*)d_in[1];
    const float* Wk = (const float*)d_in[2];
    const float* Wv = (const float*)d_in[3];
    float* out = (float*)d_out;

    cudaFuncSetAttribute(gemm_qkv,    cudaFuncAttributeMaxDynamicSharedMemorySize, NT_SMEM);
    cudaFuncSetAttribute(gemm_scores, cudaFuncAttributeMaxDynamicSharedMemorySize, NT_SMEM);
    cudaFuncSetAttribute(gemm_pv,     cudaFuncAttributeMaxDynamicSharedMemorySize, PV_SMEM);

    cvt_x<<<(long)MROWS * DIM / 4 / 256, 256>>>(x);
    cvt_w<<<dim3(DIM * DIM / 4 / 256, 3), 256>>>(Wq, Wk, Wv);

    gemm_qkv<<<dim3(MROWS / 128, NQKV / 128), 128, NT_SMEM>>>();
    gemm_scores<<<dim3(SEQ / 128, SEQ / 128, BATCH), 128, NT_SMEM>>>();
    softmax_kernel<<<BATCH * SEQ, 256>>>();
    gemm_pv<<<dim3(SEQ / 128, DIM / 128, BATCH), 128, PV_SMEM>>>(out);
}

// round 12
// speedup vs baseline: 2.1087x; 1.3861x over previous
#include <cuda_runtime.h>
#include <cuda_fp16.h>
#include <stdint.h>

#define BATCH 4
#define SEQ   2048
#define DIM   768
#define MROWS 8192            // B*S
#define NQKV  2304            // 3*DIM

// ---------------- device scratch: single fp16 planes --------------------------
__device__ __align__(128) __half g_x16[(long)MROWS * DIM];
__device__ __align__(128) __half g_w16[(long)NQKV * DIM];
__device__ __align__(128) __half g_q16[(long)MROWS * DIM];
__device__ __align__(128) __half g_k16[(long)MROWS * DIM];
__device__ __align__(128) __half g_v16[(long)MROWS * DIM];          // [b*S+s][d]
__device__ __align__(128) __half g_p16[(size_t)BATCH * SEQ * SEQ];
__device__ float g_S[(size_t)BATCH * SEQ * SEQ];

// ---------------- PTX helpers (portable, no arch-'a' features) --------------
__device__ __forceinline__ uint32_t smem_u32(const void* p) {
    uint32_t a;
    asm("{ .reg .u64 t; cvta.to.shared.u64 t, %1; cvt.u32.u64 %0, t; }"
        : "=r"(a) : "l"(p));
    return a;
}
__device__ __forceinline__ void ldsm4(uint32_t r[4], uint32_t addr) {
    asm volatile("ldmatrix.sync.aligned.m8n8.x4.shared.b16 {%0,%1,%2,%3}, [%4];"
                 : "=r"(r[0]), "=r"(r[1]), "=r"(r[2]), "=r"(r[3]) : "r"(addr));
}
__device__ __forceinline__ void ldsm4t(uint32_t r[4], uint32_t addr) {
    asm volatile("ldmatrix.sync.aligned.m8n8.x4.trans.shared.b16 {%0,%1,%2,%3}, [%4];"
                 : "=r"(r[0]), "=r"(r[1]), "=r"(r[2]), "=r"(r[3]) : "r"(addr));
}
__device__ __forceinline__ void mma16816(float d[4], const uint32_t a[4],
                                         const uint32_t b[2]) {
    asm volatile(
        "mma.sync.aligned.m16n8k16.row.col.f32.f16.f16.f32 "
        "{%0,%1,%2,%3}, {%4,%5,%6,%7}, {%8,%9}, {%0,%1,%2,%3};"
        : "+f"(d[0]), "+f"(d[1]), "+f"(d[2]), "+f"(d[3])
        : "r"(a[0]), "r"(a[1]), "r"(a[2]), "r"(a[3]), "r"(b[0]), "r"(b[1]));
}

// ---------------- smem geometry: k32 stages, double buffered -----------------
#define ROW2B   80
#define PLANE2  10240                      // 128*80
#define NT_STG  (2 * PLANE2)               // A + B = 20480
#define NT_SMEM (2 * NT_STG)               // 40960

#define VROWB   272
#define VPLANE2 (32 * VROWB)               // 8704 (V plane, 32 rows x 128 cols)
#define PV_STG  (PLANE2 + VPLANE2)         // 18944
#define PV_SMEM (2 * PV_STG)               // 37888

// ---------------- stage compute: warp tile 64x64, one k16 sub-block ----------
// 4 warps (2x2): wm,wn in {0,1}. Single fp16 planes, 1 MMA per (mi,nj).
__device__ __forceinline__ void stage_nt(uint32_t sa, uint32_t sb, int sub, int lane,
                                         int wm, int wn, float acc[4][8][4]) {
    const int lr = lane & 15;
    const uint32_t lc16 = ((lane >> 4) << 4) + (uint32_t)sub * 32;
    uint32_t bh[8][2];
#pragma unroll
    for (int j = 0; j < 4; ++j) {
        uint32_t t4[4];
        const uint32_t roff = (uint32_t)(wn * 64 + j * 16 + lr) * ROW2B + lc16;
        ldsm4(t4, sb + roff);
        bh[j*2][0] = t4[0]; bh[j*2+1][0] = t4[1];
        bh[j*2][1] = t4[2]; bh[j*2+1][1] = t4[3];
    }
#pragma unroll
    for (int mi = 0; mi < 4; ++mi) {
        uint32_t ah[4];
        const uint32_t roff = (uint32_t)(wm * 64 + mi * 16 + lr) * ROW2B + lc16;
        ldsm4(ah, sa + roff);
#pragma unroll
        for (int nj = 0; nj < 8; ++nj)
            mma16816(acc[mi][nj], ah, bh[nj]);
    }
}

__device__ __forceinline__ void stage_pv(uint32_t sa, uint32_t sv, int sub, int lane,
                                         int wm, int wn, float acc[4][8][4]) {
    const int lr = lane & 15;
    const uint32_t lc16 = (lane >> 4) << 4;
    const uint32_t pc16 = lc16 + (uint32_t)sub * 32;
    uint32_t bh[8][2];
#pragma unroll
    for (int j = 0; j < 4; ++j) {
        uint32_t t4[4];
        const uint32_t off = (uint32_t)(sub * 16 + lr) * VROWB +
                             (uint32_t)(wn * 64 + j * 16) * 2 + lc16;
        ldsm4t(t4, sv + off);
        bh[j*2][0] = t4[0]; bh[j*2][1] = t4[1];
        bh[j*2+1][0] = t4[2]; bh[j*2+1][1] = t4[3];
    }
#pragma unroll
    for (int mi = 0; mi < 4; ++mi) {
        uint32_t ah[4];
        const uint32_t roff = (uint32_t)(wm * 64 + mi * 16 + lr) * ROW2B + pc16;
        ldsm4(ah, sa + roff);
#pragma unroll
        for (int nj = 0; nj < 8; ++nj)
            mma16816(acc[mi][nj], ah, bh[nj]);
    }
}

#define ACC_INIT float acc[4][8][4];                                    \
    _Pragma("unroll") for (int _i = 0; _i < 4; ++_i)                    \
    _Pragma("unroll") for (int _j = 0; _j < 8; ++_j)                    \
    _Pragma("unroll") for (int _k = 0; _k < 4; ++_k) acc[_i][_j][_k] = 0.f;

// ---------------- k16 half-stage loaders (128 threads, register prefetch) ----
struct Frag4 { uint4 v[4]; };

__device__ __forceinline__ Frag4 ld16_nt(const __half* A, const __half* B,
                                         long lda, long ldb, int k0, int tid) {
    const long ga = (long)tid * lda + k0;
    const long gb = (long)tid * ldb + k0;
    Frag4 f;
    f.v[0] = *(const uint4*)(A + ga);
    f.v[1] = *(const uint4*)(A + ga + 8);
    f.v[2] = *(const uint4*)(B + gb);
    f.v[3] = *(const uint4*)(B + gb + 8);
    return f;
}
__device__ __forceinline__ void st16_nt(char* dsm, int stg, int sub, Frag4 f, int tid) {
    char* base = dsm + stg * NT_STG;
    const uint32_t so = (uint32_t)tid * ROW2B + (uint32_t)sub * 32;
    *(uint4*)(base + so)               = f.v[0];
    *(uint4*)(base + so + 16)          = f.v[1];
    *(uint4*)(base + PLANE2 + so)      = f.v[2];
    *(uint4*)(base + PLANE2 + so + 16) = f.v[3];
}

__device__ __forceinline__ Frag4 ld16_pv(const __half* P, const __half* V,
                                         int n0, int k0, int tid) {
    const long gp = (long)tid * SEQ + k0;
    const int vr = tid >> 3, vc = (tid & 7) * 16;
    const long gv = (long)(k0 + vr) * DIM + n0 + vc;
    Frag4 f;
    f.v[0] = *(const uint4*)(P + gp);
    f.v[1] = *(const uint4*)(P + gp + 8);
    f.v[2] = *(const uint4*)(V + gv);
    f.v[3] = *(const uint4*)(V + gv + 8);
    return f;
}
__device__ __forceinline__ void st16_pv(char* dsm, int stg, int sub, Frag4 f, int tid) {
    char* base = dsm + stg * PV_STG;
    const uint32_t so = (uint32_t)tid * ROW2B + (uint32_t)sub * 32;
    *(uint4*)(base + so)      = f.v[0];
    *(uint4*)(base + so + 16) = f.v[1];
    const int vr = tid >> 3, vc = (tid & 7) * 16;
    const uint32_t vo = (uint32_t)(sub * 16 + vr) * VROWB + (uint32_t)vc * 2;
    *(uint4*)(base + PLANE2 + vo)      = f.v[2];
    *(uint4*)(base + PLANE2 + vo + 16) = f.v[3];
}

// ---------------- kernel 0a: x -> fp16 plane ----------------------------------
__global__ __launch_bounds__(256) void cvt_x(const float* __restrict__ src) {
    const long i = ((long)blockIdx.x * 256 + threadIdx.x) * 4;
    const float4 v = *(const float4*)(src + i);
    __half h[4] = { __float2half_rn(v.x), __float2half_rn(v.y),
                    __float2half_rn(v.z), __float2half_rn(v.w) };
    *(uint2*)(g_x16 + i) = *(uint2*)h;
}

// ---------------- kernel 0b: Wq|Wk|Wv -> fp16 plane (one launch) ---------------
__global__ __launch_bounds__(256) void cvt_w(const float* __restrict__ wq,
                                             const float* __restrict__ wk,
                                             const float* __restrict__ wv) {
    const int mat = blockIdx.y;
    const float* src = (mat == 0) ? wq : ((mat == 1) ? wk : wv);
    const long i = ((long)blockIdx.x * 256 + threadIdx.x) * 4;
    const long o = (long)mat * DIM * DIM + i;
    const float4 v = *(const float4*)(src + i);
    __half h[4] = { __float2half_rn(v.x), __float2half_rn(v.y),
                    __float2half_rn(v.z), __float2half_rn(v.w) };
    *(uint2*)(g_w16 + o) = *(uint2*)h;
}

// ---------------- NT mainloop: k32 double buffer, ONE sync per 32-k ----------
#define NT_BODY(A, B, lda, ldb, NC2)                                           \
    extern __shared__ __align__(128) char dsm[];                               \
    const int tid = threadIdx.x;                                               \
    const int lane = tid & 31, wid = tid >> 5;                                 \
    const int wm = wid >> 1, wn = wid & 1;                                     \
    const uint32_t su = smem_u32(dsm);                                         \
    ACC_INIT;                                                                  \
    {                                                                          \
        Frag4 f0 = ld16_nt(A, B, lda, ldb, 0, tid);                            \
        Frag4 f1 = ld16_nt(A, B, lda, ldb, 16, tid);                           \
        st16_nt(dsm, 0, 0, f0, tid);                                           \
        st16_nt(dsm, 0, 1, f1, tid);                                           \
    }                                                                          \
    __syncthreads();                                                           \
    for (int c = 0; c < (NC2); ++c) {                                          \
        const int buf = c & 1;                                                 \
        const uint32_t sb0 = su + buf * NT_STG;                                \
        const bool more = (c + 1 < (NC2));                                     \
        Frag4 f;                                                               \
        if (more) f = ld16_nt(A, B, lda, ldb, (c + 1) * 32, tid);              \
        stage_nt(sb0, sb0 + PLANE2, 0, lane, wm, wn, acc);                     \
        if (more) {                                                            \
            st16_nt(dsm, buf ^ 1, 0, f, tid);                                  \
            f = ld16_nt(A, B, lda, ldb, (c + 1) * 32 + 16, tid);               \
        }                                                                      \
        stage_nt(sb0, sb0 + PLANE2, 1, lane, wm, wn, acc);                     \
        if (more) {                                                            \
            st16_nt(dsm, buf ^ 1, 1, f, tid);                                  \
            __syncthreads();                                                   \
        }                                                                      \
    }

// ---------------- kernel 1: QKV projection (NT) -------------------------------
__global__ __launch_bounds__(128, 2) void gemm_qkv() {
    const int m0 = blockIdx.x * 128;
    const int n0 = blockIdx.y * 128;
    NT_BODY(g_x16 + (long)m0 * DIM, g_w16 + (long)n0 * DIM, DIM, DIM, DIM / 32);

    const int mat = n0 / DIM;
    const int nl0 = n0 % DIM;
    __half* dst = (mat == 0) ? g_q16 : ((mat == 1) ? g_k16 : g_v16);
    const int r = lane >> 2, cc = (lane & 3) * 2;
#pragma unroll
    for (int mi = 0; mi < 4; ++mi)
#pragma unroll
        for (int nj = 0; nj < 8; ++nj)
#pragma unroll
            for (int h2 = 0; h2 < 2; ++h2) {
                const int m = m0 + wm * 64 + mi * 16 + r + h2 * 8;
                const int n = nl0 + wn * 64 + nj * 8 + cc;
                *(__half2*)(dst + (long)m * DIM + n) =
                    __halves2half2(__float2half_rn(acc[mi][nj][h2 * 2 + 0]),
                                   __float2half_rn(acc[mi][nj][h2 * 2 + 1]));
            }
}

// ---------------- kernel 2: causal scores (NT) --------------------------------
__global__ __launch_bounds__(128, 2) void gemm_scores() {
    const int mi_t = gridDim.x - 1 - blockIdx.x;    // longest first
    if ((int)blockIdx.y > mi_t) return;             // fully above diagonal
    const int m0 = mi_t * 128, n0 = blockIdx.y * 128, b = blockIdx.z;
    NT_BODY(g_q16 + ((long)b * SEQ + m0) * DIM,
            g_k16 + ((long)b * SEQ + n0) * DIM, DIM, DIM, DIM / 32);

    const float scale = 0.036084391824351615f;      // 1/sqrt(768)
    float* Sg = g_S + (size_t)b * SEQ * SEQ;
    const int r = lane >> 2, cc = (lane & 3) * 2;
#pragma unroll
    for (int mi = 0; mi < 4; ++mi)
#pragma unroll
        for (int nj = 0; nj < 8; ++nj)
#pragma unroll
            for (int h2 = 0; h2 < 2; ++h2) {
                const int m = m0 + wm * 64 + mi * 16 + r + h2 * 8;
                const int n = n0 + wn * 64 + nj * 8 + cc;
                float2 v = make_float2(acc[mi][nj][h2 * 2 + 0] * scale,
                                       acc[mi][nj][h2 * 2 + 1] * scale);
                *(float2*)(Sg + (size_t)m * SEQ + n) = v;
            }
}

// ---------------- kernel 3: softmax + fp16 P -----------------------------------
__global__ __launch_bounds__(256) void softmax_kernel() {
    const int rid = blockIdx.x;
    const int q = rid & (SEQ - 1);
    float* __restrict__ row = g_S + (size_t)rid * SEQ;
    __half* __restrict__ ph = g_p16 + (size_t)rid * SEQ;
    const int L = q + 1;
    const int tid = threadIdx.x;
    __shared__ float red[256];

    float m = -1e30f;
    for (int k = tid; k < L; k += 256) m = fmaxf(m, row[k]);
    red[tid] = m;
    __syncthreads();
#pragma unroll
    for (int s = 128; s > 0; s >>= 1) {
        if (tid < s) red[tid] = fmaxf(red[tid], red[tid + s]);
        __syncthreads();
    }
    m = red[0];
    __syncthreads();

    float ssum = 0.f;
    for (int k = tid; k < L; k += 256) {
        float e = __expf(row[k] - m);
        row[k] = e;
        ssum += e;
    }
    red[tid] = ssum;
    __syncthreads();
#pragma unroll
    for (int s = 128; s > 0; s >>= 1) {
        if (tid < s) red[tid] += red[tid + s];
        __syncthreads();
    }
    const float inv = 1.0f / red[0];

    for (int k = tid; k < L; k += 256)
        ph[k] = __float2half_rn(row[k] * inv);
    const int kend = (q & ~127) + 128;
    const __half z = __float2half_rn(0.f);
    for (int k = L + tid; k < kend; k += 256) ph[k] = z;
}

// ---------------- kernel 4: O = P V --------------------------------------------
__global__ __launch_bounds__(128, 2) void gemm_pv(float* __restrict__ out) {
    const int mi_t = gridDim.x - 1 - blockIdx.x;    // longest K first
    const int m0 = mi_t * 128, n0 = blockIdx.y * 128, b = blockIdx.z;
    const __half* P = g_p16 + ((size_t)b * SEQ + m0) * SEQ;
    const __half* V = g_v16 + (long)b * SEQ * DIM;

    extern __shared__ __align__(128) char dsm[];
    const int tid = threadIdx.x;
    const int lane = tid & 31, wid = tid >> 5;
    const int wm = wid >> 1, wn = wid & 1;
    const uint32_t su = smem_u32(dsm);
    ACC_INIT;
    const int NC2 = (m0 + 128) / 32;

    {
        Frag4 f0 = ld16_pv(P, V, n0, 0, tid);
        Frag4 f1 = ld16_pv(P, V, n0, 16, tid);
        st16_pv(dsm, 0, 0, f0, tid);
        st16_pv(dsm, 0, 1, f1, tid);
    }
    __syncthreads();
    for (int c = 0; c < NC2; ++c) {
        const int buf = c & 1;
        const uint32_t sb0 = su + buf * PV_STG;
        const bool more = (c + 1 < NC2);
        Frag4 f;
        if (more) f = ld16_pv(P, V, n0, (c + 1) * 32, tid);
        stage_pv(sb0, sb0 + PLANE2, 0, lane, wm, wn, acc);
        if (more) {
            st16_pv(dsm, buf ^ 1, 0, f, tid);
            f = ld16_pv(P, V, n0, (c + 1) * 32 + 16, tid);
        }
        stage_pv(sb0, sb0 + PLANE2, 1, lane, wm, wn, acc);
        if (more) {
            st16_pv(dsm, buf ^ 1, 1, f, tid);
            __syncthreads();
        }
    }

    float* Og = out + (long)b * SEQ * DIM;
    const int r = lane >> 2, cc = (lane & 3) * 2;
#pragma unroll
    for (int mi = 0; mi < 4; ++mi)
#pragma unroll
        for (int nj = 0; nj < 8; ++nj)
#pragma unroll
            for (int h2 = 0; h2 < 2; ++h2) {
                const int m = m0 + wm * 64 + mi * 16 + r + h2 * 8;
                const int n = n0 + wn * 64 + nj * 8 + cc;
                float2 v = make_float2(acc[mi][nj][h2 * 2 + 0],
                                       acc[mi][nj][h2 * 2 + 1]);
                *(float2*)(Og + (long)m * DIM + n) = v;
            }
}

// ---------------- launch ---------------------------------------------------------
extern "C" void kernel_launch(void* const* d_in, const int* in_sizes, int n_in,
                              void* d_out, int out_size) {
    const float* x  = (const float*)d_in[0];
    const float* Wq = (const float*)d_in[1];
    const float* Wk = (const float*)d_in[2];
    const float* Wv = (const float*)d_in[3];
    float* out = (float*)d_out;

    cudaFuncSetAttribute(gemm_qkv,    cudaFuncAttributeMaxDynamicSharedMemorySize, NT_SMEM);
    cudaFuncSetAttribute(gemm_scores, cudaFuncAttributeMaxDynamicSharedMemorySize, NT_SMEM);
    cudaFuncSetAttribute(gemm_pv,     cudaFuncAttributeMaxDynamicSharedMemorySize, PV_SMEM);

    cvt_x<<<(long)MROWS * DIM / 4 / 256, 256>>>(x);
    cvt_w<<<dim3(DIM * DIM / 4 / 256, 3), 256>>>(Wq, Wk, Wv);

    gemm_qkv<<<dim3(MROWS / 128, NQKV / 128), 128, NT_SMEM>>>();
    gemm_scores<<<dim3(SEQ / 128, SEQ / 128, BATCH), 128, NT_SMEM>>>();
    softmax_kernel<<<BATCH * SEQ, 256>>>();
    gemm_pv<<<dim3(SEQ / 128, DIM / 128, BATCH), 128, PV_SMEM>>>(out);
}